// round 16
// baseline (speedup 1.0000x reference)
#include <cuda_runtime.h>
#include <cstdint>

// Problem constants
#define BB 4096
#define NN 8192
#define THREADS 256
#define VECW 8
#define CTAS_PER_ROW 4
#define CHUNK (NN / CTAS_PER_ROW)               // 2048 elements per CTA
#define CHUNK_BYTES (CHUNK * 4)                 // 8192 bytes per output stream
// THREADS * VECW == CHUNK  -> exactly one fully-unrolled batch per thread

#define TAU_SYN_INV 0.5f
#define TAU_MEM_INV 0.5f
#define V_TH 1.0f
#define V_RESET 0.0f
#define INHIB (-5.0f)

// Per-row winner slot: (bits(v_new) << 32) | (0xFFFFFFFF - index).
// v_new >= 1.0 for any spiked element -> high word >= 0x3F800000 iff the row
// spiked. Positive-float bits are order-monotone; complemented index gives
// first-max (smallest index wins ties). Zero at module load; phase2 resets
// after consuming, so every graph replay sees zeros.
__device__ unsigned long long g_winner[BB];

__device__ __forceinline__ void argmax_combine(float& bv, int& bi, float ov, int oi) {
    if (ov > bv || (ov == bv && oi < bi)) { bv = ov; bi = oi; }
}

// ---- 256-bit global loads (sm_100+: LDG.E.256) ----
__device__ __forceinline__ void ldg256_cs(const float* p, unsigned u[8]) {
    asm volatile("ld.global.cs.v8.b32 {%0,%1,%2,%3,%4,%5,%6,%7}, [%8];"
                 : "=r"(u[0]), "=r"(u[1]), "=r"(u[2]), "=r"(u[3]),
                   "=r"(u[4]), "=r"(u[5]), "=r"(u[6]), "=r"(u[7])
                 : "l"(p));
}

// ---- bulk async copy SMEM -> GMEM (8KB contiguous write bursts) ----
__device__ __forceinline__ void bulk_store(void* gmem, uint32_t smem, uint32_t bytes) {
    asm volatile("cp.async.bulk.global.shared::cta.bulk_group [%0], [%1], %2;"
                 :: "l"(gmem), "r"(smem), "r"(bytes) : "memory");
}
__device__ __forceinline__ void bulk_commit() {
    asm volatile("cp.async.bulk.commit_group;" ::: "memory");
}
__device__ __forceinline__ void bulk_wait0() {
    asm volatile("cp.async.bulk.wait_group 0;" ::: "memory");
}
__device__ __forceinline__ void fence_proxy_async_cta() {
    asm volatile("fence.proxy.async.shared::cta;" ::: "memory");
}

// ---------------------------------------------------------------------------
// Kernel 1: streaming pass, 4 CTAs/row. Reads via LDG.256; all three output
// streams staged in SMEM and written as three 8KB cp.async.bulk bursts.
// Winner merged into g_winner[row] via packed atomicMax (REDG).
// ---------------------------------------------------------------------------
__global__ void __launch_bounds__(THREADS, 6)
lif_phase1(const float* __restrict__ x,
           const float* __restrict__ v,
           const float* __restrict__ icur,
           float* __restrict__ z_out,
           float* __restrict__ v_out,
           float* __restrict__ i_out) {
    __shared__ alignas(128) float s_z[CHUNK];
    __shared__ alignas(128) float s_v[CHUNK];
    __shared__ alignas(128) float s_i[CHUNK];

    const int cta     = blockIdx.x;
    const int row     = cta >> 2;          // CTAS_PER_ROW = 4
    const int quarter = cta & 3;
    const int t       = threadIdx.x;
    const int lane    = t & 31;

    const size_t base = (size_t)row * NN + (size_t)quarter * CHUNK;
    const int    goff = quarter * CHUNK + t * VECW;   // first row index of thread
    const size_t off  = base + (size_t)t * VECW;      // 32B-aligned

    // front-batched 256-bit loads: maximal MLP, no loop carry
    unsigned xu[8], vu[8], cu[8];
    ldg256_cs(x    + off, xu);
    ldg256_cs(v    + off, vu);
    ldg256_cs(icur + off, cu);

    // v_out staging = INHIB prefill (independent of loads)
    {
        float4 inh4 = make_float4(INHIB, INHIB, INHIB, INHIB);
        float4* sv4 = (float4*)(s_v + t * VECW);
        sv4[0] = inh4;
        sv4[1] = inh4;
    }

    const float NEG_INF = __int_as_float(0xff800000u);
    float best = NEG_INF;
    int   bidx = 0x7fffffff;

    float iv[8], zv[8];
    #pragma unroll
    for (int c = 0; c < VECW; c++) {
        float xf = __uint_as_float(xu[c]);
        float vf = __uint_as_float(vu[c]);
        float cf = __uint_as_float(cu[c]);
        float inew = cf + TAU_SYN_INV * (xf - cf);
        float vnew = vf + TAU_MEM_INV * (inew - vf);
        float zc   = (vnew >= V_TH) ? 1.0f : 0.0f;
        iv[c] = inew;
        zv[c] = zc;
        if (zc > 0.0f) {
            argmax_combine(best, bidx, vnew, goff + c);
        }
    }
    // stage i_new / z (vectorized STS.128, conflict-free: consecutive)
    {
        float4* si4 = (float4*)(s_i + t * VECW);
        float4* sz4 = (float4*)(s_z + t * VECW);
        si4[0] = make_float4(iv[0], iv[1], iv[2], iv[3]);
        si4[1] = make_float4(iv[4], iv[5], iv[6], iv[7]);
        sz4[0] = make_float4(zv[0], zv[1], zv[2], zv[3]);
        sz4[1] = make_float4(zv[4], zv[5], zv[6], zv[7]);
    }

    // warp argmax (first-max semantics), then one RED per spiking warp
    #pragma unroll
    for (int s = 16; s > 0; s >>= 1) {
        float ov = __shfl_xor_sync(0xffffffffu, best, s);
        int   oi = __shfl_xor_sync(0xffffffffu, bidx, s);
        argmax_combine(best, bidx, ov, oi);
    }
    if (lane == 0 && best >= V_TH) {
        unsigned long long packed =
            ((unsigned long long)__float_as_uint(best) << 32) |
            (unsigned long long)(0xFFFFFFFFu - (unsigned)bidx);
        atomicMax(&g_winner[row], packed);   // result unused -> REDG
    }

    __syncthreads();                         // all STS complete

    if (t == 0) {
        fence_proxy_async_cta();             // STS visible to async proxy
        bulk_store(z_out + base, (uint32_t)__cvta_generic_to_shared(s_z), CHUNK_BYTES);
        bulk_store(v_out + base, (uint32_t)__cvta_generic_to_shared(s_v), CHUNK_BYTES);
        bulk_store(i_out + base, (uint32_t)__cvta_generic_to_shared(s_i), CHUNK_BYTES);
        bulk_commit();
        bulk_wait0();                        // keep CTA alive until copies done
    }

#if __CUDA_ARCH__ >= 900
    cudaTriggerProgrammaticLaunchCompletion();
#endif
}

// ---------------------------------------------------------------------------
// Kernel 2 (PDL): per-row fix-up. Winner spiked -> v_after(winner) = 0;
// everything else already holds INHIB. Rare no-spike row: rewrite with v_new.
// Resets the slot for the next graph replay.
// ---------------------------------------------------------------------------
__global__ void lif_phase2(const float* __restrict__ v,
                           const float* __restrict__ i_out,
                           float* __restrict__ v_out) {
#if __CUDA_ARCH__ >= 900
    cudaGridDependencySynchronize();       // phase1 stores + REDs visible
#endif
    const int row = blockIdx.x * blockDim.x + threadIdx.x;
    if (row >= BB) return;

    unsigned long long slot = __ldcg(&g_winner[row]);
    g_winner[row] = 0ULL;                  // reset for next replay

    const unsigned vb = (unsigned)(slot >> 32);
    const size_t base = (size_t)row * NN;

    if (vb >= 0x3F800000u) {               // any spike in row
        const unsigned widx = 0xFFFFFFFFu - (unsigned)slot;
        v_out[base + widx] = V_RESET;
    } else {
        // No spikes: v_out = v_new (no resets, no inhibition). Rare; scalar ok.
        for (int n = 0; n < NN; n++) {
            float vv = v[base + n];
            float ivl = i_out[base + n];
            v_out[base + n] = vv + TAU_MEM_INV * (ivl - vv);
        }
    }
}

extern "C" void kernel_launch(void* const* d_in, const int* in_sizes, int n_in,
                              void* d_out, int out_size) {
    const float* x = (const float*)d_in[0];
    const float* v = (const float*)d_in[1];
    const float* i = (const float*)d_in[2];

    float* out   = (float*)d_out;
    float* z_out = out;                           // [B, N]
    float* v_out = out + (size_t)BB * NN;         // [B, N]
    float* i_out = out + 2 * (size_t)BB * NN;     // [B, N]

    lif_phase1<<<BB * CTAS_PER_ROW, THREADS>>>(x, v, i, z_out, v_out, i_out);

    // Phase 2 via Programmatic Dependent Launch: launch setup and dispatch
    // overlap phase1's tail; the grid-dependency sync inside provides
    // ordering + memory visibility.
    cudaLaunchAttribute attrs[1];
    attrs[0].id = cudaLaunchAttributeProgrammaticStreamSerialization;
    attrs[0].val.programmaticStreamSerializationAllowed = 1;

    cudaLaunchConfig_t cfg = {};
    cfg.gridDim  = dim3(64, 1, 1);
    cfg.blockDim = dim3(64, 1, 1);
    cfg.dynamicSmemBytes = 0;
    cfg.stream   = 0;                      // capture stream
    cfg.attrs    = attrs;
    cfg.numAttrs = 1;

    cudaLaunchKernelEx(&cfg, lif_phase2, v, i_out, v_out);
}